// round 1
// baseline (speedup 1.0000x reference)
#include <cuda_runtime.h>
#include <math.h>

// ---------------- problem constants ----------------
#define BB   64
#define NT   196
#define DD   768
#define HH   8
#define HD   96
#define RR   (BB*NT)          // 12544 rows
#define D3   (3*DD)           // 2304
#define D4   (4*DD)           // 3072
#define ATTN_SCALE 0.10206207261596577f   // 96^-0.5
#define LN_EPS 1e-5f

// ---------------- scratch (device globals; no allocations allowed) ----------------
static __device__ float g_hdw [BB*3*NT];
static __device__ float g_xemb[RR*DD];
static __device__ float g_x1  [RR*DD];
static __device__ float g_xl  [RR*DD];
static __device__ float g_qkv [(size_t)RR*D3];
static __device__ float g_v   [RR*DD];
static __device__ float g_qpv [RR*DD];
static __device__ float g_att [RR*DD];
static __device__ float g_x2  [RR*DD];
static __device__ float g_h2  [RR*DD];
static __device__ float g_fc1 [(size_t)RR*D4];
static __device__ float g_maxn[RR];
static __device__ float g_aven[RR];
static __device__ float g_s1  [RR];
static __device__ float g_gate[RR];
static __device__ float g_aveg[BB];

// ---------------- reductions ----------------
__device__ __forceinline__ float warpSum(float v){
    #pragma unroll
    for (int o=16;o;o>>=1) v += __shfl_xor_sync(0xffffffffu, v, o);
    return v;
}
__device__ __forceinline__ float warpMax(float v){
    #pragma unroll
    for (int o=16;o;o>>=1) v = fmaxf(v, __shfl_xor_sync(0xffffffffu, v, o));
    return v;
}
__device__ float blockSum(float v){
    __shared__ float sh[32];
    int lane = threadIdx.x & 31, w = threadIdx.x >> 5;
    v = warpSum(v);
    if (lane==0) sh[w] = v;
    __syncthreads();
    int nw = (blockDim.x + 31) >> 5;
    v = (threadIdx.x < nw) ? sh[threadIdx.x] : 0.f;
    if (w==0) v = warpSum(v);
    if (threadIdx.x==0) sh[0] = v;
    __syncthreads();
    v = sh[0];
    __syncthreads();
    return v;
}
__device__ float blockMax(float v){
    __shared__ float shm[32];
    int lane = threadIdx.x & 31, w = threadIdx.x >> 5;
    v = warpMax(v);
    if (lane==0) shm[w] = v;
    __syncthreads();
    int nw = (blockDim.x + 31) >> 5;
    v = (threadIdx.x < nw) ? shm[threadIdx.x] : -1e30f;
    if (w==0) v = warpMax(v);
    if (threadIdx.x==0) shm[0] = v;
    __syncthreads();
    v = shm[0];
    __syncthreads();
    return v;
}

// ---------------- patch embed ----------------
__global__ void dwconv_kernel(const float* __restrict__ img,
                              const float* __restrict__ dw_w,
                              const float* __restrict__ dw_b){
    int idx = blockIdx.x*blockDim.x + threadIdx.x;
    if (idx >= BB*3*NT) return;
    int b = idx / (3*NT);
    int rem = idx - b*3*NT;
    int c = rem / NT;
    int n = rem - c*NT;
    int oh = n / 14, ow = n - oh*14;
    const float* im = img + ((size_t)(b*3+c))*222*222;
    const float* wk = dw_w + c*256;
    float acc = 0.f;
    #pragma unroll 4
    for (int kh=0; kh<16; kh++){
        int ih = oh*16 - 1 + kh;
        if ((unsigned)ih >= 222u) continue;
        for (int kw=0; kw<16; kw++){
            int iw = ow*16 - 1 + kw;
            if ((unsigned)iw >= 222u) continue;
            acc += im[ih*222 + iw] * wk[kh*16 + kw];
        }
    }
    g_hdw[idx] = acc + dw_b[c];
}

__global__ void pointwise_kernel(const float* __restrict__ pw_w,
                                 const float* __restrict__ pw_b){
    int idx = blockIdx.x*blockDim.x + threadIdx.x;   // over RR*DD
    int row = idx / DD;
    int o   = idx - row*DD;
    int b = row / NT, n = row - b*NT;
    float h0 = g_hdw[(b*3+0)*NT + n];
    float h1 = g_hdw[(b*3+1)*NT + n];
    float h2 = g_hdw[(b*3+2)*NT + n];
    g_xemb[idx] = h0*pw_w[o*3+0] + h1*pw_w[o*3+1] + h2*pw_w[o*3+2] + pw_b[o];
}

// ---------------- x + pos_emb ----------------
__global__ void addpos_kernel(const float* __restrict__ x,
                              const float* __restrict__ pos){
    int idx = blockIdx.x*blockDim.x + threadIdx.x;   // over RR*DD
    g_x1[idx] = x[idx] + pos[idx % (NT*DD)];
}

// ---------------- LayerNorm (optionally with row stats for the gate) ----------------
template<int STATS>
__global__ __launch_bounds__(256) void ln_kernel(const float* __restrict__ X,
                                                 const float* __restrict__ sc,
                                                 const float* __restrict__ bi,
                                                 float* __restrict__ Y){
    int row = blockIdx.x;
    const float* x = X + (size_t)row*DD;
    int t = threadIdx.x;
    float v0 = x[t], v1 = x[t+256], v2 = x[t+512];
    float mean = blockSum(v0+v1+v2) * (1.f/DD);
    float d0 = v0-mean, d1 = v1-mean, d2 = v2-mean;
    float var = blockSum(d0*d0 + d1*d1 + d2*d2) * (1.f/DD);
    float inv = rsqrtf(var + LN_EPS);
    float y0 = d0*inv*sc[t    ] + bi[t    ];
    float y1 = d1*inv*sc[t+256] + bi[t+256];
    float y2 = d2*inv*sc[t+512] + bi[t+512];
    float* y = Y + (size_t)row*DD;
    y[t] = y0; y[t+256] = y1; y[t+512] = y2;
    if (STATS){
        float mx = blockMax(fmaxf(y0, fmaxf(y1, y2)));
        float sm = blockSum(y0+y1+y2);
        if (t==0){ g_maxn[row] = mx; g_aven[row] = sm * (1.f/DD); }
    }
}

// ---------------- gate: per-batch (softmax over N) ----------------
__global__ __launch_bounds__(256) void gate1_kernel(){
    int b = blockIdx.x, t = threadIdx.x;
    bool act = t < NT;
    float mn = act ? g_maxn[b*NT+t] : -1e30f;
    float av = act ? g_aven[b*NT+t] : 0.f;
    float maxg = blockMax(mn);
    float aveg = blockSum(av) * (1.f/NT);
    float t1 = maxg * mn;
    float mx = blockMax(act ? t1 : -1e30f);
    float e  = act ? expf(t1 - mx) : 0.f;
    float ss = blockSum(e);
    if (act) g_s1[b*NT+t] = e / ss;
    if (t==0) g_aveg[b] = aveg;
}

// ---------------- gate: cross-batch (softmax over B at each token) ----------------
__global__ __launch_bounds__(64) void gate2_kernel(){
    int n = blockIdx.x, b = threadIdx.x;   // 64 threads = batch dim
    float t2 = g_aveg[b] * g_aven[b*NT+n];
    float mx = blockMax(t2);
    float e  = expf(t2 - mx);
    float ss = blockSum(e);
    g_gate[b*NT+n] = g_s1[b*NT+n] * (e / ss);
}

// ---------------- v = v*gate + x_emb ;  qpv = q + v ----------------
__global__ void vqv_kernel(){
    int idx = blockIdx.x*blockDim.x + threadIdx.x;   // over RR*DD
    int row = idx / DD, d = idx - row*DD;
    size_t qbase = (size_t)row * D3;
    float vv = g_qkv[qbase + 2*DD + d] * g_gate[row] + g_xemb[idx];
    g_v[idx]   = vv;
    g_qpv[idx] = g_qkv[qbase + d] + vv;
}

// ---------------- fused attention: one block per (b,h) ----------------
#define ROWP 97
__global__ __launch_bounds__(256) void attn_kernel(){
    extern __shared__ float sm[];
    float* Qs = sm;
    float* Ks = sm +   NT*ROWP;
    float* Vs = sm + 2*NT*ROWP;
    int b = blockIdx.x, h = blockIdx.y;
    int tid = threadIdx.x;
    for (int idx = tid; idx < NT*HD; idx += 256){
        int n = idx / HD, j = idx - n*HD;
        size_t r = (size_t)(b*NT + n);
        Qs[n*ROWP+j] = g_qpv[r*DD + h*HD + j];
        Ks[n*ROWP+j] = g_qkv[r*D3 + DD + h*HD + j];
        Vs[n*ROWP+j] = g_v  [r*DD + h*HD + j];
    }
    __syncthreads();
    if (tid >= NT) return;
    float o[HD];
    #pragma unroll
    for (int j=0;j<HD;j++) o[j] = 0.f;
    float mrun = -1e30f, lrun = 0.f;
    const float* q = Qs + tid*ROWP;
    for (int m=0; m<NT; m++){
        const float* kr = Ks + m*ROWP;
        float s = 0.f;
        #pragma unroll
        for (int j=0;j<HD;j++) s += q[j]*kr[j];
        s *= ATTN_SCALE;
        float mnew  = fmaxf(mrun, s);
        float alpha = expf(mrun - mnew);
        float p     = expf(s - mnew);
        lrun = lrun*alpha + p;
        const float* vr = Vs + m*ROWP;
        #pragma unroll
        for (int j=0;j<HD;j++) o[j] = o[j]*alpha + p*vr[j];
        mrun = mnew;
    }
    float inv = 1.f / lrun;
    size_t ob = (size_t)(b*NT + tid)*DD + h*HD;
    #pragma unroll
    for (int j=0;j<HD;j++) g_att[ob + j] = o[j]*inv;
}

// ---------------- SGEMM: C[M,N] = A[M,K] @ W[N,K]^T (+bias, epilogue) ----------------
// EPI: 0 = bias only, 1 = bias+GELU(exact), 2 = bias+residual
#define GBM 128
#define GBN 128
#define GBK 8
template<int EPI>
__global__ __launch_bounds__(256) void sgemm_nt(int M, int N, int K,
        const float* __restrict__ A, const float* __restrict__ W,
        const float* __restrict__ bias, const float* __restrict__ res,
        float* __restrict__ C){
    __shared__ float As[GBK][GBM];
    __shared__ float Bs[GBK][GBN];
    int tid = threadIdx.x;
    int bm = blockIdx.y, bn = blockIdx.x;
    const float* Ab = A + (size_t)bm*GBM*K;
    const float* Wb = W + (size_t)bn*GBN*K;
    int lrow = tid >> 1;
    int lcol = (tid & 1) * 4;
    int tx = tid & 15, ty = tid >> 4;
    float acc[8][8];
    #pragma unroll
    for (int i=0;i<8;i++)
        #pragma unroll
        for (int j=0;j<8;j++) acc[i][j] = 0.f;

    for (int k0 = 0; k0 < K; k0 += GBK){
        float4 a4 = *(const float4*)(Ab + (size_t)lrow*K + k0 + lcol);
        float4 b4 = *(const float4*)(Wb + (size_t)lrow*K + k0 + lcol);
        As[lcol+0][lrow] = a4.x; As[lcol+1][lrow] = a4.y;
        As[lcol+2][lrow] = a4.z; As[lcol+3][lrow] = a4.w;
        Bs[lcol+0][lrow] = b4.x; Bs[lcol+1][lrow] = b4.y;
        Bs[lcol+2][lrow] = b4.z; Bs[lcol+3][lrow] = b4.w;
        __syncthreads();
        #pragma unroll
        for (int k=0;k<GBK;k++){
            float4 a0 = *(const float4*)&As[k][ty*8];
            float4 a1 = *(const float4*)&As[k][ty*8+4];
            float4 b0 = *(const float4*)&Bs[k][tx*8];
            float4 b1 = *(const float4*)&Bs[k][tx*8+4];
            float av[8] = {a0.x,a0.y,a0.z,a0.w,a1.x,a1.y,a1.z,a1.w};
            float bv[8] = {b0.x,b0.y,b0.z,b0.w,b1.x,b1.y,b1.z,b1.w};
            #pragma unroll
            for (int i=0;i<8;i++)
                #pragma unroll
                for (int j=0;j<8;j++) acc[i][j] += av[i]*bv[j];
        }
        __syncthreads();
    }
    #pragma unroll
    for (int i=0;i<8;i++){
        int row = bm*GBM + ty*8 + i;
        #pragma unroll
        for (int j=0;j<8;j++){
            int col = bn*GBN + tx*8 + j;
            float v = acc[i][j];
            if (bias) v += bias[col];
            if (EPI == 1){
                v = 0.5f * v * (1.0f + erff(v * 0.70710678118654752f));
            } else if (EPI == 2){
                v += res[(size_t)row*N + col];
            }
            C[(size_t)row*N + col] = v;
        }
    }
}

// ---------------- launch ----------------
extern "C" void kernel_launch(void* const* d_in, const int* in_sizes, int n_in,
                              void* d_out, int out_size){
    (void)in_sizes; (void)n_in; (void)out_size;
    const float* x      = (const float*)d_in[0];
    const float* xEem   = (const float*)d_in[1];
    const float* pos    = (const float*)d_in[2];
    const float* dw_w   = (const float*)d_in[3];
    const float* dw_b   = (const float*)d_in[4];
    const float* pw_w   = (const float*)d_in[5];
    const float* pw_b   = (const float*)d_in[6];
    const float* qkv_w  = (const float*)d_in[7];
    const float* proj_w = (const float*)d_in[8];
    const float* proj_b = (const float*)d_in[9];
    const float* ln1_s  = (const float*)d_in[10];
    const float* ln1_b  = (const float*)d_in[11];
    const float* ln2_s  = (const float*)d_in[12];
    const float* ln2_b  = (const float*)d_in[13];
    const float* fc1_w  = (const float*)d_in[14];
    const float* fc1_b  = (const float*)d_in[15];
    const float* fc2_w  = (const float*)d_in[16];
    const float* fc2_b  = (const float*)d_in[17];
    float* out = (float*)d_out;

    float *p_x1, *p_xl, *p_qkv, *p_att, *p_x2, *p_h2, *p_fc1;
    cudaGetSymbolAddress((void**)&p_x1,  g_x1);
    cudaGetSymbolAddress((void**)&p_xl,  g_xl);
    cudaGetSymbolAddress((void**)&p_qkv, g_qkv);
    cudaGetSymbolAddress((void**)&p_att, g_att);
    cudaGetSymbolAddress((void**)&p_x2,  g_x2);
    cudaGetSymbolAddress((void**)&p_h2,  g_h2);
    cudaGetSymbolAddress((void**)&p_fc1, g_fc1);

    const int EW_BLOCKS = (RR*DD)/256;   // 37632, exact

    // patch embed
    dwconv_kernel<<<(BB*3*NT + 255)/256, 256>>>(xEem, dw_w, dw_b);
    pointwise_kernel<<<EW_BLOCKS, 256>>>(pw_w, pw_b);

    // x1 = x + pos_emb ; xl = LN1(x1) with gate stats
    addpos_kernel<<<EW_BLOCKS, 256>>>(x, pos);
    ln_kernel<1><<<RR, 256>>>(p_x1, ln1_s, ln1_b, p_xl);

    // gate
    gate1_kernel<<<BB, 256>>>();
    gate2_kernel<<<NT, 64>>>();

    // qkv = xl @ qkv_w^T
    sgemm_nt<0><<<dim3(D3/GBN, RR/GBM), 256>>>(RR, D3, DD, p_xl, qkv_w,
                                               nullptr, nullptr, p_qkv);

    // v = v*gate + x_emb ; qpv = q + v
    vqv_kernel<<<EW_BLOCKS, 256>>>();

    // attention
    const int ATTN_SMEM = 3*NT*ROWP*(int)sizeof(float);   // 228144 B
    cudaFuncSetAttribute(attn_kernel, cudaFuncAttributeMaxDynamicSharedMemorySize,
                         ATTN_SMEM);
    attn_kernel<<<dim3(BB, HH), 256, ATTN_SMEM>>>();

    // x2 = x1 + proj(att)
    sgemm_nt<2><<<dim3(DD/GBN, RR/GBM), 256>>>(RR, DD, DD, p_att, proj_w,
                                               proj_b, p_x1, p_x2);

    // h2 = LN2(x2)
    ln_kernel<0><<<RR, 256>>>(p_x2, ln2_s, ln2_b, p_h2);

    // fc1 + exact GELU
    sgemm_nt<1><<<dim3(D4/GBN, RR/GBM), 256>>>(RR, D4, DD, p_h2, fc1_w,
                                               fc1_b, nullptr, p_fc1);

    // out = x2 + fc2(h)
    sgemm_nt<2><<<dim3(DD/GBN, RR/GBM), 256>>>(RR, DD, D4, p_fc1, fc2_w,
                                               fc2_b, p_x2, out);
}

// round 3
// speedup vs baseline: 2.2381x; 2.2381x over previous
#include <cuda_runtime.h>
#include <math.h>
#include <stdint.h>

// ---------------- problem constants ----------------
#define BB   64
#define NT   196
#define DD   768
#define HH   8
#define HD   96
#define RR   (BB*NT)          // 12544 rows
#define D3   (3*DD)           // 2304
#define D4   (4*DD)           // 3072
#define ATTN_SCALE 0.10206207261596577f   // 96^-0.5
#define LN_EPS 1e-5f

// ---------------- scratch (device globals; no allocations allowed) ----------------
static __device__ float g_hdw [BB*3*NT];
static __device__ float g_xemb[RR*DD];
static __device__ float g_x1  [RR*DD];
static __device__ float g_xl  [RR*DD];
static __device__ float g_qkv [(size_t)RR*D3];
static __device__ float g_v   [RR*DD];
static __device__ float g_qpv [RR*DD];
static __device__ float g_att [RR*DD];
static __device__ float g_x2  [RR*DD];
static __device__ float g_h2  [RR*DD];
static __device__ float g_fc1 [(size_t)RR*D4];
static __device__ float g_maxn[RR];
static __device__ float g_aven[RR];
static __device__ float g_s1  [RR];
static __device__ float g_gate[RR];
static __device__ float g_aveg[BB];

// ---------------- small helpers ----------------
__device__ __forceinline__ uint32_t f2tf32(float x){
    uint32_t r; asm("cvt.rna.tf32.f32 %0, %1;" : "=r"(r) : "f"(x)); return r;
}
__device__ __forceinline__ void mma_tf32(float c[4],
        uint32_t a0, uint32_t a1, uint32_t a2, uint32_t a3,
        uint32_t b0, uint32_t b1){
    asm volatile("mma.sync.aligned.m16n8k8.row.col.f32.tf32.tf32.f32 "
        "{%0,%1,%2,%3}, {%4,%5,%6,%7}, {%8,%9}, {%0,%1,%2,%3};"
        : "+f"(c[0]), "+f"(c[1]), "+f"(c[2]), "+f"(c[3])
        : "r"(a0), "r"(a1), "r"(a2), "r"(a3), "r"(b0), "r"(b1));
}

// ============================================================================
// tf32 mma.sync GEMM: C[M,N] = A[M,K] @ W[N,K]^T (+bias, epilogue)
// EPI: 0 = none/bias, 1 = bias+GELU(exact), 2 = bias+residual
// CTA tile 128x128, K-tile 32, double-buffered SMEM, 8 warps of 64x32.
// SMEM tile stride 36 floats: conflict-free fragment LDS, 16B-aligned STS.
// ============================================================================
#define TSTR 36
#define TILE_FLOATS (128*TSTR)              // 4608 floats / 18432 B
#define MMA_SMEM (4*TILE_FLOATS*4)          // 73728 B (2 stages x (A+B))

template<int EPI>
__global__ __launch_bounds__(256) void mma_gemm(int M, int N, int K,
        const float* __restrict__ A, const float* __restrict__ W,
        const float* __restrict__ bias, const float* __restrict__ res,
        float* __restrict__ C){
    extern __shared__ float smf[];
    int tid = threadIdx.x, wid = tid >> 5, lane = tid & 31;
    int bm = blockIdx.y, bn = blockIdx.x;
    const float* Ab = A + (size_t)bm*128*K;
    const float* Wb = W + (size_t)bn*128*K;
    int nk = K >> 5;

    int wm = (wid & 1) * 64;      // warp M offset in tile
    int wn = (wid >> 1) * 32;     // warp N offset in tile
    int g  = lane >> 2, tg = lane & 3;

    float c[4][4][4];
    #pragma unroll
    for (int mi=0;mi<4;mi++)
        #pragma unroll
        for (int nj=0;nj<4;nj++)
            #pragma unroll
            for (int e=0;e<4;e++) c[mi][nj][e] = 0.f;

    // staging: thread handles 4 A-chunks + 4 B-chunks of 16B per K-tile
    int rown[4], kcn[4];
    #pragma unroll
    for (int t=0;t<4;t++){ int ch = tid + 256*t; rown[t] = ch>>3; kcn[t] = ch&7; }

    float4 ra[4], rb[4];
    #pragma unroll
    for (int t=0;t<4;t++){
        ra[t] = *(const float4*)(Ab + (size_t)rown[t]*K + kcn[t]*4);
        rb[t] = *(const float4*)(Wb + (size_t)rown[t]*K + kcn[t]*4);
    }

    // store stage 0
    {
        float* As = smf; float* Bs = smf + TILE_FLOATS;
        #pragma unroll
        for (int t=0;t<4;t++){
            int off = rown[t]*TSTR + kcn[t]*4;
            *(uint4*)(As+off) = make_uint4(f2tf32(ra[t].x), f2tf32(ra[t].y), f2tf32(ra[t].z), f2tf32(ra[t].w));
            *(uint4*)(Bs+off) = make_uint4(f2tf32(rb[t].x), f2tf32(rb[t].y), f2tf32(rb[t].z), f2tf32(rb[t].w));
        }
    }
    __syncthreads();

    for (int kt=0; kt<nk; kt++){
        // prefetch next K-tile
        if (kt+1 < nk){
            int k0 = (kt+1) << 5;
            #pragma unroll
            for (int t=0;t<4;t++){
                ra[t] = *(const float4*)(Ab + (size_t)rown[t]*K + k0 + kcn[t]*4);
                rb[t] = *(const float4*)(Wb + (size_t)rown[t]*K + k0 + kcn[t]*4);
            }
        }
        const float* As = smf + (kt&1)*2*TILE_FLOATS;
        const float* Bs = As + TILE_FLOATS;
        #pragma unroll
        for (int ks=0; ks<4; ks++){
            int k = ks*8;
            uint32_t a[4][4], b[4][2];
            #pragma unroll
            for (int mi=0;mi<4;mi++){
                const float* ap = As + (wm + 16*mi + g)*TSTR + k + tg;
                a[mi][0] = __float_as_uint(ap[0]);
                a[mi][1] = __float_as_uint(ap[8*TSTR]);
                a[mi][2] = __float_as_uint(ap[4]);
                a[mi][3] = __float_as_uint(ap[8*TSTR+4]);
            }
            #pragma unroll
            for (int nj=0;nj<4;nj++){
                const float* bp = Bs + (wn + 8*nj + g)*TSTR + k + tg;
                b[nj][0] = __float_as_uint(bp[0]);
                b[nj][1] = __float_as_uint(bp[4]);
            }
            #pragma unroll
            for (int mi=0;mi<4;mi++)
                #pragma unroll
                for (int nj=0;nj<4;nj++)
                    mma_tf32(c[mi][nj], a[mi][0],a[mi][1],a[mi][2],a[mi][3], b[nj][0],b[nj][1]);
        }
        if (kt+1 < nk){
            float* As2 = smf + ((kt+1)&1)*2*TILE_FLOATS;
            float* Bs2 = As2 + TILE_FLOATS;
            #pragma unroll
            for (int t=0;t<4;t++){
                int off = rown[t]*TSTR + kcn[t]*4;
                *(uint4*)(As2+off) = make_uint4(f2tf32(ra[t].x), f2tf32(ra[t].y), f2tf32(ra[t].z), f2tf32(ra[t].w));
                *(uint4*)(Bs2+off) = make_uint4(f2tf32(rb[t].x), f2tf32(rb[t].y), f2tf32(rb[t].z), f2tf32(rb[t].w));
            }
            __syncthreads();
        }
    }

    // ---- epilogue: each thread owns 2 rows x 2 cols per (mi,nj)
    #pragma unroll
    for (int mi=0;mi<4;mi++){
        int r0 = bm*128 + wm + 16*mi + g;
        #pragma unroll
        for (int rr=0; rr<2; rr++){
            int row = r0 + rr*8;
            float* Crow = C + (size_t)row*N;
            const float* Rrow = (EPI==2) ? (res + (size_t)row*N) : (const float*)0;
            #pragma unroll
            for (int nj=0;nj<4;nj++){
                int col = bn*128 + wn + 8*nj + tg*2;
                float v0 = c[mi][nj][rr*2+0];
                float v1 = c[mi][nj][rr*2+1];
                if (bias){ v0 += __ldg(bias+col); v1 += __ldg(bias+col+1); }
                if (EPI == 1){
                    v0 = 0.5f*v0*(1.0f + erff(v0*0.70710678118654752f));
                    v1 = 0.5f*v1*(1.0f + erff(v1*0.70710678118654752f));
                } else if (EPI == 2){
                    float2 r2 = *(const float2*)(Rrow + col);
                    v0 += r2.x; v1 += r2.y;
                }
                *(float2*)(Crow + col) = make_float2(v0, v1);
            }
        }
    }
}

// ---------------- reductions ----------------
__device__ __forceinline__ float warpSum(float v){
    #pragma unroll
    for (int o=16;o;o>>=1) v += __shfl_xor_sync(0xffffffffu, v, o);
    return v;
}
__device__ __forceinline__ float warpMax(float v){
    #pragma unroll
    for (int o=16;o;o>>=1) v = fmaxf(v, __shfl_xor_sync(0xffffffffu, v, o));
    return v;
}
__device__ float blockSum(float v){
    __shared__ float sh[32];
    int lane = threadIdx.x & 31, w = threadIdx.x >> 5;
    v = warpSum(v);
    if (lane==0) sh[w] = v;
    __syncthreads();
    int nw = (blockDim.x + 31) >> 5;
    v = (threadIdx.x < nw) ? sh[threadIdx.x] : 0.f;
    if (w==0) v = warpSum(v);
    if (threadIdx.x==0) sh[0] = v;
    __syncthreads();
    v = sh[0];
    __syncthreads();
    return v;
}
__device__ float blockMax(float v){
    __shared__ float shm[32];
    int lane = threadIdx.x & 31, w = threadIdx.x >> 5;
    v = warpMax(v);
    if (lane==0) shm[w] = v;
    __syncthreads();
    int nw = (blockDim.x + 31) >> 5;
    v = (threadIdx.x < nw) ? shm[threadIdx.x] : -1e30f;
    if (w==0) v = warpMax(v);
    if (threadIdx.x==0) shm[0] = v;
    __syncthreads();
    v = shm[0];
    __syncthreads();
    return v;
}

// ---------------- patch embed ----------------
__global__ void dwconv_kernel(const float* __restrict__ img,
                              const float* __restrict__ dw_w,
                              const float* __restrict__ dw_b){
    int idx = blockIdx.x*blockDim.x + threadIdx.x;
    if (idx >= BB*3*NT) return;
    int b = idx / (3*NT);
    int rem = idx - b*3*NT;
    int c = rem / NT;
    int n = rem - c*NT;
    int oh = n / 14, ow = n - oh*14;
    const float* im = img + ((size_t)(b*3+c))*222*222;
    const float* wk = dw_w + c*256;
    float acc = 0.f;
    #pragma unroll 4
    for (int kh=0; kh<16; kh++){
        int ih = oh*16 - 1 + kh;
        if ((unsigned)ih >= 222u) continue;
        for (int kw=0; kw<16; kw++){
            int iw = ow*16 - 1 + kw;
            if ((unsigned)iw >= 222u) continue;
            acc += im[ih*222 + iw] * wk[kh*16 + kw];
        }
    }
    g_hdw[idx] = acc + dw_b[c];
}

__global__ void pointwise_kernel(const float* __restrict__ pw_w,
                                 const float* __restrict__ pw_b){
    int idx = blockIdx.x*blockDim.x + threadIdx.x;   // over RR*DD
    int row = idx / DD;
    int o   = idx - row*DD;
    int b = row / NT, n = row - b*NT;
    float h0 = g_hdw[(b*3+0)*NT + n];
    float h1 = g_hdw[(b*3+1)*NT + n];
    float h2 = g_hdw[(b*3+2)*NT + n];
    g_xemb[idx] = h0*pw_w[o*3+0] + h1*pw_w[o*3+1] + h2*pw_w[o*3+2] + pw_b[o];
}

// ---------------- x + pos_emb ----------------
__global__ void addpos_kernel(const float* __restrict__ x,
                              const float* __restrict__ pos){
    int idx = blockIdx.x*blockDim.x + threadIdx.x;   // over RR*DD
    g_x1[idx] = x[idx] + pos[idx % (NT*DD)];
}

// ---------------- LayerNorm (optionally with row stats for the gate) ----------------
template<int STATS>
__global__ __launch_bounds__(256) void ln_kernel(const float* __restrict__ X,
                                                 const float* __restrict__ sc,
                                                 const float* __restrict__ bi,
                                                 float* __restrict__ Y){
    int row = blockIdx.x;
    const float* x = X + (size_t)row*DD;
    int t = threadIdx.x;
    float v0 = x[t], v1 = x[t+256], v2 = x[t+512];
    float mean = blockSum(v0+v1+v2) * (1.f/DD);
    float d0 = v0-mean, d1 = v1-mean, d2 = v2-mean;
    float var = blockSum(d0*d0 + d1*d1 + d2*d2) * (1.f/DD);
    float inv = rsqrtf(var + LN_EPS);
    float y0 = d0*inv*sc[t    ] + bi[t    ];
    float y1 = d1*inv*sc[t+256] + bi[t+256];
    float y2 = d2*inv*sc[t+512] + bi[t+512];
    float* y = Y + (size_t)row*DD;
    y[t] = y0; y[t+256] = y1; y[t+512] = y2;
    if (STATS){
        float mx = blockMax(fmaxf(y0, fmaxf(y1, y2)));
        float sm = blockSum(y0+y1+y2);
        if (t==0){ g_maxn[row] = mx; g_aven[row] = sm * (1.f/DD); }
    }
}

// ---------------- gate: per-batch (softmax over N) ----------------
__global__ __launch_bounds__(256) void gate1_kernel(){
    int b = blockIdx.x, t = threadIdx.x;
    bool act = t < NT;
    float mn = act ? g_maxn[b*NT+t] : -1e30f;
    float av = act ? g_aven[b*NT+t] : 0.f;
    float maxg = blockMax(mn);
    float aveg = blockSum(av) * (1.f/NT);
    float t1 = maxg * mn;
    float mx = blockMax(act ? t1 : -1e30f);
    float e  = act ? expf(t1 - mx) : 0.f;
    float ss = blockSum(e);
    if (act) g_s1[b*NT+t] = e / ss;
    if (t==0) g_aveg[b] = aveg;
}

// ---------------- gate: cross-batch (softmax over B at each token) ----------------
__global__ __launch_bounds__(64) void gate2_kernel(){
    int n = blockIdx.x, b = threadIdx.x;   // 64 threads = batch dim
    float t2 = g_aveg[b] * g_aven[b*NT+n];
    float mx = blockMax(t2);
    float e  = expf(t2 - mx);
    float ss = blockSum(e);
    g_gate[b*NT+n] = g_s1[b*NT+n] * (e / ss);
}

// ---------------- v = v*gate + x_emb ;  qpv = q + v ----------------
__global__ void vqv_kernel(){
    int idx = blockIdx.x*blockDim.x + threadIdx.x;   // over RR*DD
    int row = idx / DD, d = idx - row*DD;
    size_t qbase = (size_t)row * D3;
    float vv = g_qkv[qbase + 2*DD + d] * g_gate[row] + g_xemb[idx];
    g_v[idx]   = vv;
    g_qpv[idx] = g_qkv[qbase + d] + vv;
}

// ---------------- fused attention: one block per (b,h) ----------------
#define ROWP 97
__global__ __launch_bounds__(256) void attn_kernel(){
    extern __shared__ float sm[];
    float* Qs = sm;
    float* Ks = sm +   NT*ROWP;
    float* Vs = sm + 2*NT*ROWP;
    int b = blockIdx.x, h = blockIdx.y;
    int tid = threadIdx.x;
    for (int idx = tid; idx < NT*HD; idx += 256){
        int n = idx / HD, j = idx - n*HD;
        size_t r = (size_t)(b*NT + n);
        Qs[n*ROWP+j] = g_qpv[r*DD + h*HD + j];
        Ks[n*ROWP+j] = g_qkv[r*D3 + DD + h*HD + j];
        Vs[n*ROWP+j] = g_v  [r*DD + h*HD + j];
    }
    __syncthreads();
    if (tid >= NT) return;
    float o[HD];
    #pragma unroll
    for (int j=0;j<HD;j++) o[j] = 0.f;
    float mrun = -1e30f, lrun = 0.f;
    const float* q = Qs + tid*ROWP;
    for (int m=0; m<NT; m++){
        const float* kr = Ks + m*ROWP;
        float s = 0.f;
        #pragma unroll
        for (int j=0;j<HD;j++) s += q[j]*kr[j];
        s *= ATTN_SCALE;
        float mnew  = fmaxf(mrun, s);
        float alpha = __expf(mrun - mnew);
        float p     = __expf(s - mnew);
        lrun = lrun*alpha + p;
        const float* vr = Vs + m*ROWP;
        #pragma unroll
        for (int j=0;j<HD;j++) o[j] = o[j]*alpha + p*vr[j];
        mrun = mnew;
    }
    float inv = 1.f / lrun;
    size_t ob = (size_t)(b*NT + tid)*DD + h*HD;
    #pragma unroll
    for (int j=0;j<HD;j++) g_att[ob + j] = o[j]*inv;
}

// ---------------- launch ----------------
extern "C" void kernel_launch(void* const* d_in, const int* in_sizes, int n_in,
                              void* d_out, int out_size){
    (void)in_sizes; (void)n_in; (void)out_size;
    const float* x      = (const float*)d_in[0];
    const float* xEem   = (const float*)d_in[1];
    const float* pos    = (const float*)d_in[2];
    const float* dw_w   = (const float*)d_in[3];
    const float* dw_b   = (const float*)d_in[4];
    const float* pw_w   = (const float*)d_in[5];
    const float* pw_b   = (const float*)d_in[6];
    const float* qkv_w  = (const float*)d_in[7];
    const float* proj_w = (const float*)d_in[8];
    const float* proj_b = (const float*)d_in[9];
    const float* ln1_s  = (const float*)d_in[10];
    const float* ln1_b  = (const float*)d_in[11];
    const float* ln2_s  = (const float*)d_in[12];
    const float* ln2_b  = (const float*)d_in[13];
    const float* fc1_w  = (const float*)d_in[14];
    const float* fc1_b  = (const float*)d_in[15];
    const float* fc2_w  = (const float*)d_in[16];
    const float* fc2_b  = (const float*)d_in[17];
    float* out = (float*)d_out;

    float *p_x1, *p_xl, *p_qkv, *p_att, *p_x2, *p_h2, *p_fc1;
    cudaGetSymbolAddress((void**)&p_x1,  g_x1);
    cudaGetSymbolAddress((void**)&p_xl,  g_xl);
    cudaGetSymbolAddress((void**)&p_qkv, g_qkv);
    cudaGetSymbolAddress((void**)&p_att, g_att);
    cudaGetSymbolAddress((void**)&p_x2,  g_x2);
    cudaGetSymbolAddress((void**)&p_h2,  g_h2);
    cudaGetSymbolAddress((void**)&p_fc1, g_fc1);

    cudaFuncSetAttribute(mma_gemm<0>, cudaFuncAttributeMaxDynamicSharedMemorySize, MMA_SMEM);
    cudaFuncSetAttribute(mma_gemm<1>, cudaFuncAttributeMaxDynamicSharedMemorySize, MMA_SMEM);
    cudaFuncSetAttribute(mma_gemm<2>, cudaFuncAttributeMaxDynamicSharedMemorySize, MMA_SMEM);

    const int EW_BLOCKS = (RR*DD)/256;   // 37632, exact

    // patch embed
    dwconv_kernel<<<(BB*3*NT + 255)/256, 256>>>(xEem, dw_w, dw_b);
    pointwise_kernel<<<EW_BLOCKS, 256>>>(pw_w, pw_b);

    // x1 = x + pos_emb ; xl = LN1(x1) with gate stats
    addpos_kernel<<<EW_BLOCKS, 256>>>(x, pos);
    ln_kernel<1><<<RR, 256>>>(p_x1, ln1_s, ln1_b, p_xl);

    // gate
    gate1_kernel<<<BB, 256>>>();
    gate2_kernel<<<NT, 64>>>();

    // qkv = xl @ qkv_w^T   (no bias)
    mma_gemm<0><<<dim3(D3/128, RR/128), 256, MMA_SMEM>>>(RR, D3, DD, p_xl, qkv_w,
                                                         nullptr, nullptr, p_qkv);

    // v = v*gate + x_emb ; qpv = q + v
    vqv_kernel<<<EW_BLOCKS, 256>>>();

    // attention
    const int ATTN_SMEM = 3*NT*ROWP*(int)sizeof(float);   // 228144 B
    cudaFuncSetAttribute(attn_kernel, cudaFuncAttributeMaxDynamicSharedMemorySize,
                         ATTN_SMEM);
    attn_kernel<<<dim3(BB, HH), 256, ATTN_SMEM>>>();

    // x2 = x1 + proj(att)
    mma_gemm<2><<<dim3(DD/128, RR/128), 256, MMA_SMEM>>>(RR, DD, DD, p_att, proj_w,
                                                         proj_b, p_x1, p_x2);

    // h2 = LN2(x2)
    ln_kernel<0><<<RR, 256>>>(p_x2, ln2_s, ln2_b, p_h2);

    // fc1 + exact GELU
    mma_gemm<1><<<dim3(D4/128, RR/128), 256, MMA_SMEM>>>(RR, D4, DD, p_h2, fc1_w,
                                                         fc1_b, nullptr, p_fc1);

    // out = x2 + fc2(h)
    mma_gemm<2><<<dim3(DD/128, RR/128), 256, MMA_SMEM>>>(RR, DD, D4, p_fc1, fc2_w,
                                                         fc2_b, p_x2, out);
}

// round 4
// speedup vs baseline: 2.9585x; 1.3219x over previous
#include <cuda_runtime.h>
#include <math.h>
#include <stdint.h>

// ---------------- problem constants ----------------
#define BB   64
#define NT   196
#define DD   768
#define HH   8
#define HD   96
#define RR   (BB*NT)          // 12544 rows
#define D3   (3*DD)           // 2304
#define D4   (4*DD)           // 3072
#define ATTN_SCALE 0.10206207261596577f   // 96^-0.5
#define LN_EPS 1e-5f

// ---------------- scratch (device globals; no allocations allowed) ----------------
static __device__ float g_hdw [BB*3*NT];
static __device__ float g_xemb[RR*DD];
static __device__ float g_x1  [RR*DD];
static __device__ float g_xl  [RR*DD];
static __device__ float g_qkv [(size_t)RR*D3];
static __device__ float g_v   [RR*DD];
static __device__ float g_qpv [RR*DD];
static __device__ float g_att [RR*DD];
static __device__ float g_x2  [RR*DD];
static __device__ float g_h2  [RR*DD];
static __device__ float g_fc1 [(size_t)RR*D4];
static __device__ float g_maxn[RR];
static __device__ float g_aven[RR];
static __device__ float g_s1  [RR];
static __device__ float g_gate[RR];
static __device__ float g_aveg[BB];
// tf32-rounded weight copies
static __device__ float g_wqkv[(size_t)D3*DD];
static __device__ float g_wproj[(size_t)DD*DD];
static __device__ float g_wfc1[(size_t)D4*DD];
static __device__ float g_wfc2[(size_t)DD*D4];

// ---------------- small helpers ----------------
__device__ __forceinline__ uint32_t f2tf32(float x){
    uint32_t r; asm("cvt.rna.tf32.f32 %0, %1;" : "=r"(r) : "f"(x)); return r;
}
__device__ __forceinline__ float rndtf(float x){ return __uint_as_float(f2tf32(x)); }

__device__ __forceinline__ uint32_t smem_u32(const void* p){
    uint32_t a;
    asm("{ .reg .u64 t; cvta.to.shared.u64 t, %1; cvt.u32.u64 %0, t; }" : "=r"(a) : "l"(p));
    return a;
}
__device__ __forceinline__ void cp16(uint32_t dst, const float* src){
    asm volatile("cp.async.cg.shared.global [%0], [%1], 16;" :: "r"(dst), "l"(src));
}
__device__ __forceinline__ void cp_commit(){ asm volatile("cp.async.commit_group;" ::: "memory"); }
template<int N> __device__ __forceinline__ void cp_wait(){
    asm volatile("cp.async.wait_group %0;" :: "n"(N) : "memory");
}
__device__ __forceinline__ void mma_tf32(float c[4],
        uint32_t a0, uint32_t a1, uint32_t a2, uint32_t a3,
        uint32_t b0, uint32_t b1){
    asm volatile("mma.sync.aligned.m16n8k8.row.col.f32.tf32.tf32.f32 "
        "{%0,%1,%2,%3}, {%4,%5,%6,%7}, {%8,%9}, {%0,%1,%2,%3};"
        : "+f"(c[0]), "+f"(c[1]), "+f"(c[2]), "+f"(c[3])
        : "r"(a0), "r"(a1), "r"(a2), "r"(a3), "r"(b0), "r"(b1));
}

// ---------------- weight tf32 pre-round ----------------
__global__ void round_tf32_kernel(const float* __restrict__ s, float* __restrict__ d, int n){
    int i = blockIdx.x*blockDim.x + threadIdx.x;
    if (i < n) d[i] = rndtf(s[i]);
}

// ============================================================================
// tf32 mma.sync GEMM, cp.async 3-stage: C[M,N] = A[M,K] @ W[N,K]^T
// A and W must be tf32-pre-rounded fp32. EPI: 0 none/bias, 1 bias+GELU(round),
// 2 bias+residual. CTA tile 128x128, K-tile 32, 8 warps of 64x32.
// ============================================================================
#define NSTG 3
#define TSTR 36
#define TFL  (128*TSTR)                 // floats per (A or B) stage tile
#define STGF (2*TFL)                    // floats per stage (A+B)
#define MMA_SMEM (NSTG*STGF*4)          // 110592 B

template<int EPI>
__global__ __launch_bounds__(256,2) void mma_gemm(int M, int N, int K,
        const float* __restrict__ A, const float* __restrict__ W,
        const float* __restrict__ bias, const float* __restrict__ res,
        float* __restrict__ C){
    extern __shared__ float smf[];
    uint32_t sbase = smem_u32(smf);
    int tid = threadIdx.x, wid = tid >> 5, lane = tid & 31;
    int bm = blockIdx.y, bn = blockIdx.x;
    const float* Ab = A + (size_t)bm*128*K;
    const float* Wb = W + (size_t)bn*128*K;
    int nk = K >> 5;

    int wm = (wid & 1) * 64;
    int wn = (wid >> 1) * 32;
    int g  = lane >> 2, tg = lane & 3;

    int rown[4], kcn[4];
    #pragma unroll
    for (int t=0;t<4;t++){ int ch = tid + 256*t; rown[t] = ch>>3; kcn[t] = ch&7; }

    // prologue: issue stages 0,1
    #pragma unroll
    for (int s=0; s<2; s++){
        uint32_t sA = sbase + (uint32_t)(s*STGF*4);
        uint32_t sB = sA + TFL*4;
        int k0 = s << 5;
        #pragma unroll
        for (int t=0;t<4;t++){
            uint32_t off = (uint32_t)(rown[t]*TSTR + kcn[t]*4)*4u;
            cp16(sA + off, Ab + (size_t)rown[t]*K + k0 + kcn[t]*4);
            cp16(sB + off, Wb + (size_t)rown[t]*K + k0 + kcn[t]*4);
        }
        cp_commit();
    }

    float c[4][4][4];
    #pragma unroll
    for (int mi=0;mi<4;mi++)
        #pragma unroll
        for (int nj=0;nj<4;nj++)
            #pragma unroll
            for (int e=0;e<4;e++) c[mi][nj][e] = 0.f;

    for (int kt=0; kt<nk; kt++){
        if (kt < nk-1) cp_wait<1>(); else cp_wait<0>();
        __syncthreads();
        if (kt+2 < nk){
            int s = (kt+2)%NSTG;
            int k0 = (kt+2) << 5;
            uint32_t sA = sbase + (uint32_t)(s*STGF*4);
            uint32_t sB = sA + TFL*4;
            #pragma unroll
            for (int t=0;t<4;t++){
                uint32_t off = (uint32_t)(rown[t]*TSTR + kcn[t]*4)*4u;
                cp16(sA + off, Ab + (size_t)rown[t]*K + k0 + kcn[t]*4);
                cp16(sB + off, Wb + (size_t)rown[t]*K + k0 + kcn[t]*4);
            }
            cp_commit();
        }
        const float* As = smf + (kt%NSTG)*STGF;
        const float* Bs = As + TFL;
        #pragma unroll
        for (int ks=0; ks<4; ks++){
            int k = ks*8;
            uint32_t a[4][4], b[4][2];
            #pragma unroll
            for (int mi=0;mi<4;mi++){
                const float* ap = As + (wm + 16*mi + g)*TSTR + k + tg;
                a[mi][0] = __float_as_uint(ap[0]);
                a[mi][1] = __float_as_uint(ap[8*TSTR]);
                a[mi][2] = __float_as_uint(ap[4]);
                a[mi][3] = __float_as_uint(ap[8*TSTR+4]);
            }
            #pragma unroll
            for (int nj=0;nj<4;nj++){
                const float* bp = Bs + (wn + 8*nj + g)*TSTR + k + tg;
                b[nj][0] = __float_as_uint(bp[0]);
                b[nj][1] = __float_as_uint(bp[4]);
            }
            #pragma unroll
            for (int mi=0;mi<4;mi++)
                #pragma unroll
                for (int nj=0;nj<4;nj++)
                    mma_tf32(c[mi][nj], a[mi][0],a[mi][1],a[mi][2],a[mi][3], b[nj][0],b[nj][1]);
        }
    }

    // ---- epilogue
    #pragma unroll
    for (int mi=0;mi<4;mi++){
        int r0 = bm*128 + wm + 16*mi + g;
        #pragma unroll
        for (int rr=0; rr<2; rr++){
            int row = r0 + rr*8;
            float* Crow = C + (size_t)row*N;
            const float* Rrow = (EPI==2) ? (res + (size_t)row*N) : (const float*)0;
            #pragma unroll
            for (int nj=0;nj<4;nj++){
                int col = bn*128 + wn + 8*nj + tg*2;
                float v0 = c[mi][nj][rr*2+0];
                float v1 = c[mi][nj][rr*2+1];
                if (bias){ v0 += __ldg(bias+col); v1 += __ldg(bias+col+1); }
                if (EPI == 1){
                    v0 = 0.5f*v0*(1.0f + erff(v0*0.70710678118654752f));
                    v1 = 0.5f*v1*(1.0f + erff(v1*0.70710678118654752f));
                    v0 = rndtf(v0); v1 = rndtf(v1);
                } else if (EPI == 2){
                    float2 r2 = *(const float2*)(Rrow + col);
                    v0 += r2.x; v1 += r2.y;
                }
                *(float2*)(Crow + col) = make_float2(v0, v1);
            }
        }
    }
}

// ---------------- reductions ----------------
__device__ __forceinline__ float warpSum(float v){
    #pragma unroll
    for (int o=16;o;o>>=1) v += __shfl_xor_sync(0xffffffffu, v, o);
    return v;
}
__device__ __forceinline__ float warpMax(float v){
    #pragma unroll
    for (int o=16;o;o>>=1) v = fmaxf(v, __shfl_xor_sync(0xffffffffu, v, o));
    return v;
}
__device__ float blockSum(float v){
    __shared__ float sh[32];
    int lane = threadIdx.x & 31, w = threadIdx.x >> 5;
    v = warpSum(v);
    if (lane==0) sh[w] = v;
    __syncthreads();
    int nw = (blockDim.x + 31) >> 5;
    v = (threadIdx.x < nw) ? sh[threadIdx.x] : 0.f;
    if (w==0) v = warpSum(v);
    if (threadIdx.x==0) sh[0] = v;
    __syncthreads();
    v = sh[0];
    __syncthreads();
    return v;
}
__device__ float blockMax(float v){
    __shared__ float shm[32];
    int lane = threadIdx.x & 31, w = threadIdx.x >> 5;
    v = warpMax(v);
    if (lane==0) shm[w] = v;
    __syncthreads();
    int nw = (blockDim.x + 31) >> 5;
    v = (threadIdx.x < nw) ? shm[threadIdx.x] : -1e30f;
    if (w==0) v = warpMax(v);
    if (threadIdx.x==0) shm[0] = v;
    __syncthreads();
    v = shm[0];
    __syncthreads();
    return v;
}

// ---------------- patch embed ----------------
__global__ void dwconv_kernel(const float* __restrict__ img,
                              const float* __restrict__ dw_w,
                              const float* __restrict__ dw_b){
    int idx = blockIdx.x*blockDim.x + threadIdx.x;
    if (idx >= BB*3*NT) return;
    int b = idx / (3*NT);
    int rem = idx - b*3*NT;
    int c = rem / NT;
    int n = rem - c*NT;
    int oh = n / 14, ow = n - oh*14;
    const float* im = img + ((size_t)(b*3+c))*222*222;
    const float* wk = dw_w + c*256;
    float acc = 0.f;
    #pragma unroll 4
    for (int kh=0; kh<16; kh++){
        int ih = oh*16 - 1 + kh;
        if ((unsigned)ih >= 222u) continue;
        for (int kw=0; kw<16; kw++){
            int iw = ow*16 - 1 + kw;
            if ((unsigned)iw >= 222u) continue;
            acc += im[ih*222 + iw] * wk[kh*16 + kw];
        }
    }
    g_hdw[idx] = acc + dw_b[c];
}

__global__ void pointwise_kernel(const float* __restrict__ pw_w,
                                 const float* __restrict__ pw_b){
    int idx = blockIdx.x*blockDim.x + threadIdx.x;   // over RR*DD
    int row = idx / DD;
    int o   = idx - row*DD;
    int b = row / NT, n = row - b*NT;
    float h0 = g_hdw[(b*3+0)*NT + n];
    float h1 = g_hdw[(b*3+1)*NT + n];
    float h2 = g_hdw[(b*3+2)*NT + n];
    g_xemb[idx] = h0*pw_w[o*3+0] + h1*pw_w[o*3+1] + h2*pw_w[o*3+2] + pw_b[o];
}

// ---------------- LN1 fused with addpos + gate stats (xl rounded to tf32) ----
__global__ __launch_bounds__(256) void ln1_kernel(const float* __restrict__ X,
                                                  const float* __restrict__ pos,
                                                  const float* __restrict__ sc,
                                                  const float* __restrict__ bi){
    int row = blockIdx.x;
    int n = row % NT;
    const float* x = X + (size_t)row*DD;
    const float* p = pos + (size_t)n*DD;
    int t = threadIdx.x;
    float v0 = x[t]+p[t], v1 = x[t+256]+p[t+256], v2 = x[t+512]+p[t+512];
    float* x1 = g_x1 + (size_t)row*DD;
    x1[t] = v0; x1[t+256] = v1; x1[t+512] = v2;
    float mean = blockSum(v0+v1+v2) * (1.f/DD);
    float d0 = v0-mean, d1 = v1-mean, d2 = v2-mean;
    float var = blockSum(d0*d0 + d1*d1 + d2*d2) * (1.f/DD);
    float inv = rsqrtf(var + LN_EPS);
    float y0 = d0*inv*sc[t    ] + bi[t    ];
    float y1 = d1*inv*sc[t+256] + bi[t+256];
    float y2 = d2*inv*sc[t+512] + bi[t+512];
    float* y = g_xl + (size_t)row*DD;
    y[t] = rndtf(y0); y[t+256] = rndtf(y1); y[t+512] = rndtf(y2);
    float mx = blockMax(fmaxf(y0, fmaxf(y1, y2)));
    float sm = blockSum(y0+y1+y2);
    if (t==0){ g_maxn[row] = mx; g_aven[row] = sm * (1.f/DD); }
}

// ---------------- LN2 (h2 rounded) ----------------
__global__ __launch_bounds__(256) void ln2_kernel(const float* __restrict__ X,
                                                  const float* __restrict__ sc,
                                                  const float* __restrict__ bi,
                                                  float* __restrict__ Y){
    int row = blockIdx.x;
    const float* x = X + (size_t)row*DD;
    int t = threadIdx.x;
    float v0 = x[t], v1 = x[t+256], v2 = x[t+512];
    float mean = blockSum(v0+v1+v2) * (1.f/DD);
    float d0 = v0-mean, d1 = v1-mean, d2 = v2-mean;
    float var = blockSum(d0*d0 + d1*d1 + d2*d2) * (1.f/DD);
    float inv = rsqrtf(var + LN_EPS);
    float* y = Y + (size_t)row*DD;
    y[t    ] = rndtf(d0*inv*sc[t    ] + bi[t    ]);
    y[t+256] = rndtf(d1*inv*sc[t+256] + bi[t+256]);
    y[t+512] = rndtf(d2*inv*sc[t+512] + bi[t+512]);
}

// ---------------- gate: per-batch (softmax over N) ----------------
__global__ __launch_bounds__(256) void gate1_kernel(){
    int b = blockIdx.x, t = threadIdx.x;
    bool act = t < NT;
    float mn = act ? g_maxn[b*NT+t] : -1e30f;
    float av = act ? g_aven[b*NT+t] : 0.f;
    float maxg = blockMax(mn);
    float aveg = blockSum(av) * (1.f/NT);
    float t1 = maxg * mn;
    float mx = blockMax(act ? t1 : -1e30f);
    float e  = act ? expf(t1 - mx) : 0.f;
    float ss = blockSum(e);
    if (act) g_s1[b*NT+t] = e / ss;
    if (t==0) g_aveg[b] = aveg;
}

// ---------------- gate: cross-batch (softmax over B at each token) --------
__global__ __launch_bounds__(64) void gate2_kernel(){
    int n = blockIdx.x, b = threadIdx.x;   // 64 threads = batch dim
    float t2 = g_aveg[b] * g_aven[b*NT+n];
    float mx = blockMax(t2);
    float e  = expf(t2 - mx);
    float ss = blockSum(e);
    g_gate[b*NT+n] = g_s1[b*NT+n] * (e / ss);
}

// ---------------- v = v*gate + x_emb ;  qpv = q + v ----------------
__global__ void vqv_kernel(){
    int idx = blockIdx.x*blockDim.x + threadIdx.x;   // over RR*DD
    int row = idx / DD, d = idx - row*DD;
    size_t qbase = (size_t)row * D3;
    float vv = g_qkv[qbase + 2*DD + d] * g_gate[row] + g_xemb[idx];
    g_v[idx]   = vv;
    g_qpv[idx] = g_qkv[qbase + d] + vv;
}

// ---------------- fused attention: one block per (b,h), m-unrolled x4 ------
#define ROWP 97
__global__ __launch_bounds__(256) void attn_kernel(){
    extern __shared__ float sm[];
    float* Qs = sm;
    float* Ks = sm +   NT*ROWP;
    float* Vs = sm + 2*NT*ROWP;
    int b = blockIdx.x, h = blockIdx.y;
    int tid = threadIdx.x;
    for (int idx = tid; idx < NT*HD; idx += 256){
        int n = idx / HD, j = idx - n*HD;
        size_t r = (size_t)(b*NT + n);
        Qs[n*ROWP+j] = g_qpv[r*DD + h*HD + j];
        Ks[n*ROWP+j] = g_qkv[r*D3 + DD + h*HD + j];
        Vs[n*ROWP+j] = g_v  [r*DD + h*HD + j];
    }
    __syncthreads();
    if (tid >= NT) return;
    float o[HD];
    #pragma unroll
    for (int j=0;j<HD;j++) o[j] = 0.f;
    float mrun = -1e30f, lrun = 0.f;
    const float* q = Qs + tid*ROWP;
    for (int m0=0; m0<NT; m0+=4){
        const float* k0 = Ks + m0*ROWP;
        const float* k1 = k0 + ROWP;
        const float* k2 = k1 + ROWP;
        const float* k3 = k2 + ROWP;
        float s0=0.f, s1=0.f, s2=0.f, s3=0.f;
        #pragma unroll
        for (int j=0;j<HD;j++){
            float qj = q[j];
            s0 += qj*k0[j]; s1 += qj*k1[j]; s2 += qj*k2[j]; s3 += qj*k3[j];
        }
        s0 *= ATTN_SCALE; s1 *= ATTN_SCALE; s2 *= ATTN_SCALE; s3 *= ATTN_SCALE;
        float mnew = fmaxf(fmaxf(fmaxf(s0,s1), fmaxf(s2,s3)), mrun);
        float alpha = __expf(mrun - mnew);
        float p0 = __expf(s0 - mnew);
        float p1 = __expf(s1 - mnew);
        float p2 = __expf(s2 - mnew);
        float p3 = __expf(s3 - mnew);
        lrun = lrun*alpha + (p0+p1+p2+p3);
        const float* v0 = Vs + m0*ROWP;
        const float* v1 = v0 + ROWP;
        const float* v2 = v1 + ROWP;
        const float* v3 = v2 + ROWP;
        #pragma unroll
        for (int j=0;j<HD;j++)
            o[j] = o[j]*alpha + (p0*v0[j] + p1*v1[j] + p2*v2[j] + p3*v3[j]);
        mrun = mnew;
    }
    float inv = 1.f / lrun;
    size_t ob = (size_t)(b*NT + tid)*DD + h*HD;
    #pragma unroll
    for (int j=0;j<HD;j++) g_att[ob + j] = rndtf(o[j]*inv);
}

// ---------------- launch ----------------
extern "C" void kernel_launch(void* const* d_in, const int* in_sizes, int n_in,
                              void* d_out, int out_size){
    (void)in_sizes; (void)n_in; (void)out_size;
    const float* x      = (const float*)d_in[0];
    const float* xEem   = (const float*)d_in[1];
    const float* pos    = (const float*)d_in[2];
    const float* dw_w   = (const float*)d_in[3];
    const float* dw_b   = (const float*)d_in[4];
    const float* pw_w   = (const float*)d_in[5];
    const float* pw_b   = (const float*)d_in[6];
    const float* qkv_w  = (const float*)d_in[7];
    const float* proj_w = (const float*)d_in[8];
    const float* proj_b = (const float*)d_in[9];
    const float* ln1_s  = (const float*)d_in[10];
    const float* ln1_b  = (const float*)d_in[11];
    const float* ln2_s  = (const float*)d_in[12];
    const float* ln2_b  = (const float*)d_in[13];
    const float* fc1_w  = (const float*)d_in[14];
    const float* fc1_b  = (const float*)d_in[15];
    const float* fc2_w  = (const float*)d_in[16];
    const float* fc2_b  = (const float*)d_in[17];
    float* out = (float*)d_out;

    float *p_x1, *p_xl, *p_qkv, *p_att, *p_x2, *p_h2, *p_fc1;
    float *p_wqkv, *p_wproj, *p_wfc1, *p_wfc2;
    cudaGetSymbolAddress((void**)&p_x1,  g_x1);
    cudaGetSymbolAddress((void**)&p_xl,  g_xl);
    cudaGetSymbolAddress((void**)&p_qkv, g_qkv);
    cudaGetSymbolAddress((void**)&p_att, g_att);
    cudaGetSymbolAddress((void**)&p_x2,  g_x2);
    cudaGetSymbolAddress((void**)&p_h2,  g_h2);
    cudaGetSymbolAddress((void**)&p_fc1, g_fc1);
    cudaGetSymbolAddress((void**)&p_wqkv, g_wqkv);
    cudaGetSymbolAddress((void**)&p_wproj, g_wproj);
    cudaGetSymbolAddress((void**)&p_wfc1, g_wfc1);
    cudaGetSymbolAddress((void**)&p_wfc2, g_wfc2);

    cudaFuncSetAttribute(mma_gemm<0>, cudaFuncAttributeMaxDynamicSharedMemorySize, MMA_SMEM);
    cudaFuncSetAttribute(mma_gemm<1>, cudaFuncAttributeMaxDynamicSharedMemorySize, MMA_SMEM);
    cudaFuncSetAttribute(mma_gemm<2>, cudaFuncAttributeMaxDynamicSharedMemorySize, MMA_SMEM);

    const int EW_BLOCKS = (RR*DD)/256;   // 37632, exact

    // weight pre-round (tf32 rna)
    round_tf32_kernel<<<(D3*DD)/256, 256>>>(qkv_w, p_wqkv, D3*DD);
    round_tf32_kernel<<<(DD*DD)/256, 256>>>(proj_w, p_wproj, DD*DD);
    round_tf32_kernel<<<(D4*DD)/256, 256>>>(fc1_w, p_wfc1, D4*DD);
    round_tf32_kernel<<<(DD*D4)/256, 256>>>(fc2_w, p_wfc2, DD*D4);

    // patch embed
    dwconv_kernel<<<(BB*3*NT + 255)/256, 256>>>(xEem, dw_w, dw_b);
    pointwise_kernel<<<EW_BLOCKS, 256>>>(pw_w, pw_b);

    // x1 = x + pos ; xl = round(LN1(x1)) with gate stats
    ln1_kernel<<<RR, 256>>>(x, pos, ln1_s, ln1_b);

    // gate
    gate1_kernel<<<BB, 256>>>();
    gate2_kernel<<<NT, 64>>>();

    // qkv = xl @ qkv_w^T   (no bias)
    mma_gemm<0><<<dim3(D3/128, RR/128), 256, MMA_SMEM>>>(RR, D3, DD, p_xl, p_wqkv,
                                                         nullptr, nullptr, p_qkv);

    // v = v*gate + x_emb ; qpv = q + v
    vqv_kernel<<<EW_BLOCKS, 256>>>();

    // attention
    const int ATTN_SMEM = 3*NT*ROWP*(int)sizeof(float);   // 228144 B
    cudaFuncSetAttribute(attn_kernel, cudaFuncAttributeMaxDynamicSharedMemorySize,
                         ATTN_SMEM);
    attn_kernel<<<dim3(BB, HH), 256, ATTN_SMEM>>>();

    // x2 = x1 + proj(att)
    mma_gemm<2><<<dim3(DD/128, RR/128), 256, MMA_SMEM>>>(RR, DD, DD, p_att, p_wproj,
                                                         proj_b, p_x1, p_x2);

    // h2 = round(LN2(x2))
    ln2_kernel<<<RR, 256>>>(p_x2, ln2_s, ln2_b, p_h2);

    // fc1 + exact GELU (rounded)
    mma_gemm<1><<<dim3(D4/128, RR/128), 256, MMA_SMEM>>>(RR, D4, DD, p_h2, p_wfc1,
                                                         fc1_b, nullptr, p_fc1);

    // out = x2 + fc2(h)
    mma_gemm<2><<<dim3(DD/128, RR/128), 256, MMA_SMEM>>>(RR, DD, D4, p_fc1, p_wfc2,
                                                         fc2_b, p_x2, out);
}

// round 5
// speedup vs baseline: 3.1772x; 1.0739x over previous
#include <cuda_runtime.h>
#include <cuda_fp16.h>
#include <math.h>
#include <stdint.h>

// ---------------- problem constants ----------------
#define BB   64
#define NT   196
#define DD   768
#define HH   8
#define HD   96
#define RR   (BB*NT)          // 12544 rows
#define D3   (3*DD)           // 2304
#define D4   (4*DD)           // 3072
#define ATTN_SCALE 0.10206207261596577f   // 96^-0.5
#define LN_EPS 1e-5f

// ---------------- scratch (device globals; no allocations allowed) ----------------
static __device__ float  g_hdw [BB*3*NT];
static __device__ float  g_xemb[RR*DD];
static __device__ float  g_x1  [RR*DD];
static __device__ __half g_xl_h[RR*DD];
static __device__ float  g_qkv [(size_t)RR*D3];
static __device__ float  g_v   [RR*DD];
static __device__ float  g_qpv [RR*DD];
static __device__ __half g_att_h[RR*DD];
static __device__ float  g_x2  [RR*DD];
static __device__ __half g_h2_h[RR*DD];
static __device__ __half g_fc1_h[(size_t)RR*D4];
static __device__ float  g_maxn[RR];
static __device__ float  g_aven[RR];
static __device__ float  g_s1  [RR];
static __device__ float  g_gate[RR];
static __device__ float  g_aveg[BB];
// fp16 weight copies
static __device__ __half g_wqkv_h [(size_t)D3*DD];
static __device__ __half g_wproj_h[(size_t)DD*DD];
static __device__ __half g_wfc1_h [(size_t)D4*DD];
static __device__ __half g_wfc2_h [(size_t)DD*D4];

// ---------------- small helpers ----------------
__device__ __forceinline__ uint32_t smem_u32(const void* p){
    uint32_t a;
    asm("{ .reg .u64 t; cvta.to.shared.u64 t, %1; cvt.u32.u64 %0, t; }" : "=r"(a) : "l"(p));
    return a;
}
__device__ __forceinline__ void cp16(uint32_t dst, const void* src){
    asm volatile("cp.async.cg.shared.global [%0], [%1], 16;" :: "r"(dst), "l"(src));
}
__device__ __forceinline__ void cp_commit(){ asm volatile("cp.async.commit_group;" ::: "memory"); }
template<int N> __device__ __forceinline__ void cp_wait(){
    asm volatile("cp.async.wait_group %0;" :: "n"(N) : "memory");
}
__device__ __forceinline__ void mma_f16(float c[4],
        uint32_t a0, uint32_t a1, uint32_t a2, uint32_t a3,
        uint32_t b0, uint32_t b1){
    asm volatile("mma.sync.aligned.m16n8k16.row.col.f32.f16.f16.f32 "
        "{%0,%1,%2,%3}, {%4,%5,%6,%7}, {%8,%9}, {%0,%1,%2,%3};"
        : "+f"(c[0]), "+f"(c[1]), "+f"(c[2]), "+f"(c[3])
        : "r"(a0), "r"(a1), "r"(a2), "r"(a3), "r"(b0), "r"(b1));
}

// ---------------- weight fp16 conversion ----------------
__global__ void f2h_kernel(const float* __restrict__ s, __half* __restrict__ d, int n){
    int i = blockIdx.x*blockDim.x + threadIdx.x;
    if (i < n) d[i] = __float2half_rn(s[i]);
}

// ============================================================================
// fp16 mma.sync GEMM, cp.async 4-stage: C[M,N] = A[M,K] @ W[N,K]^T
// A, W are fp16; accumulate fp32. EPI: 0 none/bias (fp32 out),
// 1 bias+GELU (HALF out), 2 bias+residual (fp32 out).
// CTA tile 128x128, K-tile 32, 8 warps of 64x32, m16n8k16.
// ============================================================================
#define NSTG 4
#define TSH  40                       // smem row stride in halves (80B)
#define TILEB (128*TSH*2)             // bytes per matrix per stage = 10240
#define STGB  (2*TILEB)               // 20480
#define MMA_SMEM (NSTG*STGB)          // 81920

template<int EPI>
__global__ __launch_bounds__(256,2) void hgemm(int M, int N, int K,
        const __half* __restrict__ A, const __half* __restrict__ W,
        const float* __restrict__ bias, const float* __restrict__ res,
        void* __restrict__ Cout){
    extern __shared__ char smc[];
    uint32_t sbase = smem_u32(smc);
    __half* sh = (__half*)smc;
    int tid = threadIdx.x, wid = tid >> 5, lane = tid & 31;
    int bm = blockIdx.y, bn = blockIdx.x;
    const __half* Ab = A + (size_t)bm*128*K;
    const __half* Wb = W + (size_t)bn*128*K;
    int nk = K >> 5;

    int wm = (wid & 1) * 64;
    int wn = (wid >> 1) * 32;
    int g  = lane >> 2, tg = lane & 3;

    // staging: tid<128 -> A row tid ; tid>=128 -> B row tid-128 ; 4x16B chunks/row
    int srow = tid & 127;
    const __half* gsrc = ((tid < 128) ? Ab : Wb) + (size_t)srow*K;
    uint32_t sdst = ((tid < 128) ? 0u : (uint32_t)TILEB) + (uint32_t)srow*(TSH*2);

    // prologue: stages 0..NSTG-2
    #pragma unroll
    for (int s=0; s<NSTG-1; s++){
        uint32_t base = sbase + s*STGB + sdst;
        const __half* gp = gsrc + (s << 5);
        #pragma unroll
        for (int kc=0; kc<4; kc++) cp16(base + kc*16, gp + kc*8);
        cp_commit();
    }

    float c[4][4][4];
    #pragma unroll
    for (int mi=0;mi<4;mi++)
        #pragma unroll
        for (int nj=0;nj<4;nj++)
            #pragma unroll
            for (int e=0;e<4;e++) c[mi][nj][e] = 0.f;

    for (int kt=0; kt<nk; kt++){
        cp_wait<NSTG-2>();
        __syncthreads();
        // issue stage kt+NSTG-1 (empty commit keeps group accounting at tail)
        if (kt + NSTG-1 < nk){
            int s = (kt + NSTG-1) % NSTG;
            uint32_t base = sbase + s*STGB + sdst;
            const __half* gp = gsrc + ((kt + NSTG-1) << 5);
            #pragma unroll
            for (int kc=0; kc<4; kc++) cp16(base + kc*16, gp + kc*8);
        }
        cp_commit();

        const __half* As = sh + (size_t)(kt % NSTG) * (STGB/2);
        const __half* Bs = As + TILEB/2;
        #pragma unroll
        for (int ks=0; ks<2; ks++){
            int kb = ks*16;
            uint32_t a[4][4], b[4][2];
            #pragma unroll
            for (int mi=0;mi<4;mi++){
                const __half* ap = As + (wm + 16*mi + g)*TSH + kb + 2*tg;
                a[mi][0] = *(const uint32_t*)(ap);
                a[mi][1] = *(const uint32_t*)(ap + 8*TSH);
                a[mi][2] = *(const uint32_t*)(ap + 8);
                a[mi][3] = *(const uint32_t*)(ap + 8*TSH + 8);
            }
            #pragma unroll
            for (int nj=0;nj<4;nj++){
                const __half* bp = Bs + (wn + 8*nj + g)*TSH + kb + 2*tg;
                b[nj][0] = *(const uint32_t*)(bp);
                b[nj][1] = *(const uint32_t*)(bp + 8);
            }
            #pragma unroll
            for (int mi=0;mi<4;mi++)
                #pragma unroll
                for (int nj=0;nj<4;nj++)
                    mma_f16(c[mi][nj], a[mi][0],a[mi][1],a[mi][2],a[mi][3], b[nj][0],b[nj][1]);
        }
    }

    // ---- epilogue: per (mi,nj): rows g,g+8 ; cols 2tg,2tg+1
    #pragma unroll
    for (int mi=0;mi<4;mi++){
        int r0 = bm*128 + wm + 16*mi + g;
        #pragma unroll
        for (int rr=0; rr<2; rr++){
            int row = r0 + rr*8;
            #pragma unroll
            for (int nj=0;nj<4;nj++){
                int col = bn*128 + wn + 8*nj + tg*2;
                float v0 = c[mi][nj][rr*2+0];
                float v1 = c[mi][nj][rr*2+1];
                if (bias){ v0 += __ldg(bias+col); v1 += __ldg(bias+col+1); }
                if (EPI == 1){
                    v0 = 0.5f*v0*(1.0f + erff(v0*0.70710678118654752f));
                    v1 = 0.5f*v1*(1.0f + erff(v1*0.70710678118654752f));
                    __half* Crow = (__half*)Cout + (size_t)row*N;
                    *(__half2*)(Crow + col) = __floats2half2_rn(v0, v1);
                } else if (EPI == 2){
                    const float* Rrow = res + (size_t)row*N;
                    float2 r2 = *(const float2*)(Rrow + col);
                    v0 += r2.x; v1 += r2.y;
                    float* Crow = (float*)Cout + (size_t)row*N;
                    *(float2*)(Crow + col) = make_float2(v0, v1);
                } else {
                    float* Crow = (float*)Cout + (size_t)row*N;
                    *(float2*)(Crow + col) = make_float2(v0, v1);
                }
            }
        }
    }
}

// ---------------- reductions ----------------
__device__ __forceinline__ float warpSum(float v){
    #pragma unroll
    for (int o=16;o;o>>=1) v += __shfl_xor_sync(0xffffffffu, v, o);
    return v;
}
__device__ __forceinline__ float warpMax(float v){
    #pragma unroll
    for (int o=16;o;o>>=1) v = fmaxf(v, __shfl_xor_sync(0xffffffffu, v, o));
    return v;
}
__device__ float blockSum(float v){
    __shared__ float sh[32];
    int lane = threadIdx.x & 31, w = threadIdx.x >> 5;
    v = warpSum(v);
    if (lane==0) sh[w] = v;
    __syncthreads();
    int nw = (blockDim.x + 31) >> 5;
    v = (threadIdx.x < nw) ? sh[threadIdx.x] : 0.f;
    if (w==0) v = warpSum(v);
    if (threadIdx.x==0) sh[0] = v;
    __syncthreads();
    v = sh[0];
    __syncthreads();
    return v;
}
__device__ float blockMax(float v){
    __shared__ float shm[32];
    int lane = threadIdx.x & 31, w = threadIdx.x >> 5;
    v = warpMax(v);
    if (lane==0) shm[w] = v;
    __syncthreads();
    int nw = (blockDim.x + 31) >> 5;
    v = (threadIdx.x < nw) ? shm[threadIdx.x] : -1e30f;
    if (w==0) v = warpMax(v);
    if (threadIdx.x==0) shm[0] = v;
    __syncthreads();
    v = shm[0];
    __syncthreads();
    return v;
}

// ---------------- patch embed ----------------
__global__ void dwconv_kernel(const float* __restrict__ img,
                              const float* __restrict__ dw_w,
                              const float* __restrict__ dw_b){
    int idx = blockIdx.x*blockDim.x + threadIdx.x;
    if (idx >= BB*3*NT) return;
    int b = idx / (3*NT);
    int rem = idx - b*3*NT;
    int c = rem / NT;
    int n = rem - c*NT;
    int oh = n / 14, ow = n - oh*14;
    const float* im = img + ((size_t)(b*3+c))*222*222;
    const float* wk = dw_w + c*256;
    float acc = 0.f;
    #pragma unroll 4
    for (int kh=0; kh<16; kh++){
        int ih = oh*16 - 1 + kh;
        if ((unsigned)ih >= 222u) continue;
        for (int kw=0; kw<16; kw++){
            int iw = ow*16 - 1 + kw;
            if ((unsigned)iw >= 222u) continue;
            acc += im[ih*222 + iw] * wk[kh*16 + kw];
        }
    }
    g_hdw[idx] = acc + dw_b[c];
}

__global__ void pointwise_kernel(const float* __restrict__ pw_w,
                                 const float* __restrict__ pw_b){
    int idx = blockIdx.x*blockDim.x + threadIdx.x;   // over RR*DD
    int row = idx / DD;
    int o   = idx - row*DD;
    int b = row / NT, n = row - b*NT;
    float h0 = g_hdw[(b*3+0)*NT + n];
    float h1 = g_hdw[(b*3+1)*NT + n];
    float h2 = g_hdw[(b*3+2)*NT + n];
    g_xemb[idx] = h0*pw_w[o*3+0] + h1*pw_w[o*3+1] + h2*pw_w[o*3+2] + pw_b[o];
}

// ---------------- LN1 fused with addpos + gate stats (xl -> half) ----------
__global__ __launch_bounds__(256) void ln1_kernel(const float* __restrict__ X,
                                                  const float* __restrict__ pos,
                                                  const float* __restrict__ sc,
                                                  const float* __restrict__ bi){
    int row = blockIdx.x;
    int n = row % NT;
    const float* x = X + (size_t)row*DD;
    const float* p = pos + (size_t)n*DD;
    int t = threadIdx.x;
    float v0 = x[t]+p[t], v1 = x[t+256]+p[t+256], v2 = x[t+512]+p[t+512];
    float* x1 = g_x1 + (size_t)row*DD;
    x1[t] = v0; x1[t+256] = v1; x1[t+512] = v2;
    float mean = blockSum(v0+v1+v2) * (1.f/DD);
    float d0 = v0-mean, d1 = v1-mean, d2 = v2-mean;
    float var = blockSum(d0*d0 + d1*d1 + d2*d2) * (1.f/DD);
    float inv = rsqrtf(var + LN_EPS);
    float y0 = d0*inv*sc[t    ] + bi[t    ];
    float y1 = d1*inv*sc[t+256] + bi[t+256];
    float y2 = d2*inv*sc[t+512] + bi[t+512];
    __half* y = g_xl_h + (size_t)row*DD;
    y[t] = __float2half_rn(y0); y[t+256] = __float2half_rn(y1); y[t+512] = __float2half_rn(y2);
    float mx = blockMax(fmaxf(y0, fmaxf(y1, y2)));
    float sm = blockSum(y0+y1+y2);
    if (t==0){ g_maxn[row] = mx; g_aven[row] = sm * (1.f/DD); }
}

// ---------------- LN2 (h2 -> half) ----------------
__global__ __launch_bounds__(256) void ln2_kernel(const float* __restrict__ X,
                                                  const float* __restrict__ sc,
                                                  const float* __restrict__ bi){
    int row = blockIdx.x;
    const float* x = X + (size_t)row*DD;
    int t = threadIdx.x;
    float v0 = x[t], v1 = x[t+256], v2 = x[t+512];
    float mean = blockSum(v0+v1+v2) * (1.f/DD);
    float d0 = v0-mean, d1 = v1-mean, d2 = v2-mean;
    float var = blockSum(d0*d0 + d1*d1 + d2*d2) * (1.f/DD);
    float inv = rsqrtf(var + LN_EPS);
    __half* y = g_h2_h + (size_t)row*DD;
    y[t    ] = __float2half_rn(d0*inv*sc[t    ] + bi[t    ]);
    y[t+256] = __float2half_rn(d1*inv*sc[t+256] + bi[t+256]);
    y[t+512] = __float2half_rn(d2*inv*sc[t+512] + bi[t+512]);
}

// ---------------- gate: per-batch (softmax over N) ----------------
__global__ __launch_bounds__(256) void gate1_kernel(){
    int b = blockIdx.x, t = threadIdx.x;
    bool act = t < NT;
    float mn = act ? g_maxn[b*NT+t] : -1e30f;
    float av = act ? g_aven[b*NT+t] : 0.f;
    float maxg = blockMax(mn);
    float aveg = blockSum(av) * (1.f/NT);
    float t1 = maxg * mn;
    float mx = blockMax(act ? t1 : -1e30f);
    float e  = act ? expf(t1 - mx) : 0.f;
    float ss = blockSum(e);
    if (act) g_s1[b*NT+t] = e / ss;
    if (t==0) g_aveg[b] = aveg;
}

// ---------------- gate: cross-batch (softmax over B at each token) --------
__global__ __launch_bounds__(64) void gate2_kernel(){
    int n = blockIdx.x, b = threadIdx.x;   // 64 threads = batch dim
    float t2 = g_aveg[b] * g_aven[b*NT+n];
    float mx = blockMax(t2);
    float e  = expf(t2 - mx);
    float ss = blockSum(e);
    g_gate[b*NT+n] = g_s1[b*NT+n] * (e / ss);
}

// ---------------- v = v*gate + x_emb ;  qpv = q + v ----------------
__global__ void vqv_kernel(){
    int idx = blockIdx.x*blockDim.x + threadIdx.x;   // over RR*DD
    int row = idx / DD, d = idx - row*DD;
    size_t qbase = (size_t)row * D3;
    float vv = g_qkv[qbase + 2*DD + d] * g_gate[row] + g_xemb[idx];
    g_v[idx]   = vv;
    g_qpv[idx] = g_qkv[qbase + d] + vv;
}

// ---------------- fused attention: one block per (b,h), m-unrolled x4 ------
#define ROWP 97
__global__ __launch_bounds__(256) void attn_kernel(){
    extern __shared__ float sm[];
    float* Qs = sm;
    float* Ks = sm +   NT*ROWP;
    float* Vs = sm + 2*NT*ROWP;
    int b = blockIdx.x, h = blockIdx.y;
    int tid = threadIdx.x;
    for (int idx = tid; idx < NT*HD; idx += 256){
        int n = idx / HD, j = idx - n*HD;
        size_t r = (size_t)(b*NT + n);
        Qs[n*ROWP+j] = g_qpv[r*DD + h*HD + j];
        Ks[n*ROWP+j] = g_qkv[r*D3 + DD + h*HD + j];
        Vs[n*ROWP+j] = g_v  [r*DD + h*HD + j];
    }
    __syncthreads();
    if (tid >= NT) return;
    float o[HD];
    #pragma unroll
    for (int j=0;j<HD;j++) o[j] = 0.f;
    float mrun = -1e30f, lrun = 0.f;
    const float* q = Qs + tid*ROWP;
    for (int m0=0; m0<NT; m0+=4){
        const float* k0 = Ks + m0*ROWP;
        const float* k1 = k0 + ROWP;
        const float* k2 = k1 + ROWP;
        const float* k3 = k2 + ROWP;
        float s0=0.f, s1=0.f, s2=0.f, s3=0.f;
        #pragma unroll
        for (int j=0;j<HD;j++){
            float qj = q[j];
            s0 += qj*k0[j]; s1 += qj*k1[j]; s2 += qj*k2[j]; s3 += qj*k3[j];
        }
        s0 *= ATTN_SCALE; s1 *= ATTN_SCALE; s2 *= ATTN_SCALE; s3 *= ATTN_SCALE;
        float mnew = fmaxf(fmaxf(fmaxf(s0,s1), fmaxf(s2,s3)), mrun);
        float alpha = __expf(mrun - mnew);
        float p0 = __expf(s0 - mnew);
        float p1 = __expf(s1 - mnew);
        float p2 = __expf(s2 - mnew);
        float p3 = __expf(s3 - mnew);
        lrun = lrun*alpha + (p0+p1+p2+p3);
        const float* v0 = Vs + m0*ROWP;
        const float* v1 = v0 + ROWP;
        const float* v2 = v1 + ROWP;
        const float* v3 = v2 + ROWP;
        #pragma unroll
        for (int j=0;j<HD;j++)
            o[j] = o[j]*alpha + (p0*v0[j] + p1*v1[j] + p2*v2[j] + p3*v3[j]);
        mrun = mnew;
    }
    float inv = 1.f / lrun;
    size_t ob = (size_t)(b*NT + tid)*DD + h*HD;
    #pragma unroll
    for (int j=0;j<HD;j++) g_att_h[ob + j] = __float2half_rn(o[j]*inv);
}

// ---------------- launch ----------------
extern "C" void kernel_launch(void* const* d_in, const int* in_sizes, int n_in,
                              void* d_out, int out_size){
    (void)in_sizes; (void)n_in; (void)out_size;
    const float* x      = (const float*)d_in[0];
    const float* xEem   = (const float*)d_in[1];
    const float* pos    = (const float*)d_in[2];
    const float* dw_w   = (const float*)d_in[3];
    const float* dw_b   = (const float*)d_in[4];
    const float* pw_w   = (const float*)d_in[5];
    const float* pw_b   = (const float*)d_in[6];
    const float* qkv_w  = (const float*)d_in[7];
    const float* proj_w = (const float*)d_in[8];
    const float* proj_b = (const float*)d_in[9];
    const float* ln1_s  = (const float*)d_in[10];
    const float* ln1_b  = (const float*)d_in[11];
    const float* ln2_s  = (const float*)d_in[12];
    const float* ln2_b  = (const float*)d_in[13];
    const float* fc1_w  = (const float*)d_in[14];
    const float* fc1_b  = (const float*)d_in[15];
    const float* fc2_w  = (const float*)d_in[16];
    const float* fc2_b  = (const float*)d_in[17];
    float* out = (float*)d_out;

    float  *p_x1, *p_qkv, *p_x2;
    __half *p_xl, *p_att, *p_h2, *p_fc1;
    __half *p_wqkv, *p_wproj, *p_wfc1, *p_wfc2;
    cudaGetSymbolAddress((void**)&p_x1,  g_x1);
    cudaGetSymbolAddress((void**)&p_xl,  g_xl_h);
    cudaGetSymbolAddress((void**)&p_qkv, g_qkv);
    cudaGetSymbolAddress((void**)&p_att, g_att_h);
    cudaGetSymbolAddress((void**)&p_x2,  g_x2);
    cudaGetSymbolAddress((void**)&p_h2,  g_h2_h);
    cudaGetSymbolAddress((void**)&p_fc1, g_fc1_h);
    cudaGetSymbolAddress((void**)&p_wqkv, g_wqkv_h);
    cudaGetSymbolAddress((void**)&p_wproj, g_wproj_h);
    cudaGetSymbolAddress((void**)&p_wfc1, g_wfc1_h);
    cudaGetSymbolAddress((void**)&p_wfc2, g_wfc2_h);

    cudaFuncSetAttribute(hgemm<0>, cudaFuncAttributeMaxDynamicSharedMemorySize, MMA_SMEM);
    cudaFuncSetAttribute(hgemm<1>, cudaFuncAttributeMaxDynamicSharedMemorySize, MMA_SMEM);
    cudaFuncSetAttribute(hgemm<2>, cudaFuncAttributeMaxDynamicSharedMemorySize, MMA_SMEM);

    const int EW_BLOCKS = (RR*DD)/256;   // 37632, exact

    // weight fp16 conversion
    f2h_kernel<<<(D3*DD)/256, 256>>>(qkv_w, p_wqkv, D3*DD);
    f2h_kernel<<<(DD*DD)/256, 256>>>(proj_w, p_wproj, DD*DD);
    f2h_kernel<<<(D4*DD)/256, 256>>>(fc1_w, p_wfc1, D4*DD);
    f2h_kernel<<<(DD*D4)/256, 256>>>(fc2_w, p_wfc2, DD*D4);

    // patch embed
    dwconv_kernel<<<(BB*3*NT + 255)/256, 256>>>(xEem, dw_w, dw_b);
    pointwise_kernel<<<EW_BLOCKS, 256>>>(pw_w, pw_b);

    // x1 = x + pos ; xl = half(LN1(x1)) with gate stats
    ln1_kernel<<<RR, 256>>>(x, pos, ln1_s, ln1_b);

    // gate
    gate1_kernel<<<BB, 256>>>();
    gate2_kernel<<<NT, 64>>>();

    // qkv = xl @ qkv_w^T (fp32 out, no bias)
    hgemm<0><<<dim3(D3/128, RR/128), 256, MMA_SMEM>>>(RR, D3, DD, p_xl, p_wqkv,
                                                      nullptr, nullptr, p_qkv);

    // v = v*gate + x_emb ; qpv = q + v
    vqv_kernel<<<EW_BLOCKS, 256>>>();

    // attention (writes half)
    const int ATTN_SMEM = 3*NT*ROWP*(int)sizeof(float);   // 228144 B
    cudaFuncSetAttribute(attn_kernel, cudaFuncAttributeMaxDynamicSharedMemorySize,
                         ATTN_SMEM);
    attn_kernel<<<dim3(BB, HH), 256, ATTN_SMEM>>>();

    // x2 = x1 + proj(att)
    hgemm<2><<<dim3(DD/128, RR/128), 256, MMA_SMEM>>>(RR, DD, DD, p_att, p_wproj,
                                                      proj_b, p_x1, p_x2);

    // h2 = half(LN2(x2))
    ln2_kernel<<<RR, 256>>>(p_x2, ln2_s, ln2_b);

    // fc1 + exact GELU -> half
    hgemm<1><<<dim3(D4/128, RR/128), 256, MMA_SMEM>>>(RR, D4, DD, p_h2, p_wfc1,
                                                      fc1_b, nullptr, p_fc1);

    // out = x2 + fc2(h)
    hgemm<2><<<dim3(DD/128, RR/128), 256, MMA_SMEM>>>(RR, DD, D4, p_fc1, p_wfc2,
                                                      fc2_b, p_x2, out);
}